// round 8
// baseline (speedup 1.0000x reference)
#include <cuda_runtime.h>
#include <cuda_bf16.h>
#include <math_constants.h>
#include <cstdint>

// Problem constants
#define S_LEN 1024
#define B_SZ  8
#define H_DIM 1024
#define NHEAD 16
#define HDIM  64
#define M_ROWS (B_SZ * S_LEN)   // 8192

// Scratch for projected Q/K/V, [B*S, H] with m = b*S_LEN + s.
__device__ float g_QL[(size_t)M_ROWS * H_DIM];
__device__ float g_KL[(size_t)M_ROWS * H_DIM];
__device__ float g_VL[(size_t)M_ROWS * H_DIM];

// ===========================================================================
// Helpers
// ===========================================================================
__device__ __forceinline__ uint32_t smem_to_u32(const void* p) {
    uint32_t a;
    asm("{ .reg .u64 t; cvta.to.shared.u64 t, %1; cvt.u32.u64 %0, t; }"
        : "=r"(a) : "l"(p));
    return a;
}

// mma.sync m16n8k16 row.col f32.bf16.bf16.f32  (sm_80+, no 'a' target needed)
__device__ __forceinline__ void mma16816(float* c, const uint32_t* a, const uint32_t* b)
{
    asm volatile(
        "mma.sync.aligned.m16n8k16.row.col.f32.bf16.bf16.f32 "
        "{%0,%1,%2,%3},{%4,%5,%6,%7},{%8,%9},{%0,%1,%2,%3};"
        : "+f"(c[0]), "+f"(c[1]), "+f"(c[2]), "+f"(c[3])
        : "r"(a[0]), "r"(a[1]), "r"(a[2]), "r"(a[3]), "r"(b[0]), "r"(b[1]));
}

__device__ __forceinline__ void ldsm4(uint32_t* r, uint32_t addr)
{
    asm volatile("ldmatrix.sync.aligned.m8n8.x4.shared.b16 {%0,%1,%2,%3},[%4];"
                 : "=r"(r[0]), "=r"(r[1]), "=r"(r[2]), "=r"(r[3]) : "r"(addr));
}

// Packed fp32x2 helpers (attention SIMT kernel)
__device__ __forceinline__ unsigned long long ffma2(
    unsigned long long a, unsigned long long b, unsigned long long c)
{
    unsigned long long d;
    asm("fma.rn.f32x2 %0, %1, %2, %3;" : "=l"(d) : "l"(a), "l"(b), "l"(c));
    return d;
}
__device__ __forceinline__ unsigned long long pack2(float x)
{
    unsigned long long d;
    asm("mov.b64 %0, {%1, %1};" : "=l"(d) : "f"(x));
    return d;
}
__device__ __forceinline__ void unpack2(unsigned long long v, float& lo, float& hi)
{
    asm("mov.b64 {%0, %1}, %2;" : "=f"(lo), "=f"(hi) : "l"(v));
}

// fp32 -> bf16 hi/lo split of a float4; outputs packed bf16x2 words.
__device__ __forceinline__ void cvt4_split(
    float4 v, uint32_t& h0, uint32_t& h1, uint32_t& l0, uint32_t& l1)
{
    __nv_bfloat16 hx = __float2bfloat16_rn(v.x);
    __nv_bfloat16 hy = __float2bfloat16_rn(v.y);
    __nv_bfloat16 hz = __float2bfloat16_rn(v.z);
    __nv_bfloat16 hw = __float2bfloat16_rn(v.w);
    h0 = (uint32_t)__bfloat16_as_ushort(hx) | ((uint32_t)__bfloat16_as_ushort(hy) << 16);
    h1 = (uint32_t)__bfloat16_as_ushort(hz) | ((uint32_t)__bfloat16_as_ushort(hw) << 16);
    __nv_bfloat16 lx = __float2bfloat16_rn(v.x - __bfloat162float(hx));
    __nv_bfloat16 ly = __float2bfloat16_rn(v.y - __bfloat162float(hy));
    __nv_bfloat16 lz = __float2bfloat16_rn(v.z - __bfloat162float(hz));
    __nv_bfloat16 lw = __float2bfloat16_rn(v.w - __bfloat162float(hw));
    l0 = (uint32_t)__bfloat16_as_ushort(lx) | ((uint32_t)__bfloat16_as_ushort(ly) << 16);
    l1 = (uint32_t)__bfloat16_as_ushort(lz) | ((uint32_t)__bfloat16_as_ushort(lw) << 16);
}

// ===========================================================================
// Projection GEMM via mma.sync (HMMA), split-bf16 3-term compensation.
//   Y[m][n] = sum_k X'[m][k] * W[n][k] + bias[n]
//   CTA tile 128x128, K-chunk 32, 8 warps as 2(m)x4(n) -> 64x32 warp tiles.
//   SMEM rows padded to 40 bf16 (80B) -> ldmatrix conflict-free.
//   grid = (8, 64, 3): x = n-tile, y = m-tile, z = projection id.
// ===========================================================================
#define PROW 40   // padded row stride in bf16 elems (80B)

__global__ __launch_bounds__(256) void proj_mma_kernel(
    const float* __restrict__ Xq, const float* __restrict__ Xk,
    const float* __restrict__ Xv,
    const float* __restrict__ Wq, const float* __restrict__ bq,
    const float* __restrict__ Wk, const float* __restrict__ bk,
    const float* __restrict__ Wv, const float* __restrict__ bv)
{
    __shared__ __align__(16) uint16_t sAhi[128 * PROW];
    __shared__ __align__(16) uint16_t sAlo[128 * PROW];
    __shared__ __align__(16) uint16_t sBhi[128 * PROW];
    __shared__ __align__(16) uint16_t sBlo[128 * PROW];

    const int z = blockIdx.z;
    const float* X    = (z == 0) ? Xq : ((z == 1) ? Xk : Xv);
    const float* W    = (z == 0) ? Wq : ((z == 1) ? Wk : Wv);
    const float* bias = (z == 0) ? bq : ((z == 1) ? bk : bv);
    float* out        = (z == 0) ? g_QL : ((z == 1) ? g_KL : g_VL);

    const int m0 = blockIdx.y * 128;
    const int n0 = blockIdx.x * 128;

    // A rows: m = b*S + s. A 128-row tile stays within one b.
    const float* Abase = X + ((size_t)((m0 & (S_LEN - 1)) * B_SZ + (m0 >> 10))) * H_DIM;
    const float* Bbase = W + (size_t)n0 * H_DIM;

    const int tid  = threadIdx.x;
    const int lane = tid & 31;
    const int wid  = tid >> 5;
    const int warp_m = wid & 1;        // 0..1 -> 64-row strip
    const int warp_n = wid >> 1;       // 0..3 -> 32-col strip

    const uint32_t uAhi = smem_to_u32(sAhi);
    const uint32_t uAlo = smem_to_u32(sAlo);
    const uint32_t uBhi = smem_to_u32(sBhi);
    const uint32_t uBlo = smem_to_u32(sBlo);

    float acc[4][4][4];
    #pragma unroll
    for (int i = 0; i < 4; i++)
        #pragma unroll
        for (int j = 0; j < 4; j++)
            #pragma unroll
            for (int k = 0; k < 4; k++) acc[i][j][k] = 0.0f;

    // staging assignment: 2 threads per row, 16 floats each
    const int sr = tid >> 1;
    const int hf = tid & 1;

    // ldmatrix addresses (element offsets precomputed as bytes below)
    const int a_row = warp_m * 64 + (lane & 15);
    const uint32_t a_colb = (uint32_t)((lane >> 4) << 4);       // 0 or 16 bytes
    const int b_row = warp_n * 32 + (lane & 7) + ((lane & 16) ? 8 : 0);
    const uint32_t b_colb = (uint32_t)((lane & 8) ? 16 : 0);

    for (int c = 0; c < H_DIM / 32; c++) {
        // ---- stage chunk c: fp32 -> bf16 hi/lo into SMEM ----
        {
            const float* pa = Abase + (size_t)sr * (B_SZ * H_DIM) + c * 32 + hf * 16;
            const float* pb = Bbase + (size_t)sr * H_DIM          + c * 32 + hf * 16;
            uint16_t* ah = &sAhi[sr * PROW + hf * 16];
            uint16_t* al = &sAlo[sr * PROW + hf * 16];
            uint16_t* bh = &sBhi[sr * PROW + hf * 16];
            uint16_t* bl = &sBlo[sr * PROW + hf * 16];
            #pragma unroll
            for (int i = 0; i < 4; i++) {
                float4 va = *reinterpret_cast<const float4*>(pa + i * 4);
                uint32_t h0, h1, l0, l1;
                cvt4_split(va, h0, h1, l0, l1);
                *reinterpret_cast<uint2*>(ah + i * 4) = make_uint2(h0, h1);
                *reinterpret_cast<uint2*>(al + i * 4) = make_uint2(l0, l1);
                float4 vb = *reinterpret_cast<const float4*>(pb + i * 4);
                cvt4_split(vb, h0, h1, l0, l1);
                *reinterpret_cast<uint2*>(bh + i * 4) = make_uint2(h0, h1);
                *reinterpret_cast<uint2*>(bl + i * 4) = make_uint2(l0, l1);
            }
        }
        __syncthreads();

        // ---- mma phase: 2 k16 steps ----
        #pragma unroll
        for (int ks = 0; ks < 2; ks++) {
            const uint32_t kb = (uint32_t)(ks * 32);
            uint32_t ahi[4][4], alo[4][4], bhi[4][2], blo[4][2];
            #pragma unroll
            for (int mt = 0; mt < 4; mt++) {
                uint32_t off = (uint32_t)((a_row + mt * 16) * (PROW * 2)) + kb + a_colb;
                ldsm4(ahi[mt], uAhi + off);
                ldsm4(alo[mt], uAlo + off);
            }
            {
                uint32_t t[4];
                uint32_t off0 = (uint32_t)(b_row * (PROW * 2)) + kb + b_colb;
                uint32_t off1 = (uint32_t)((b_row + 16) * (PROW * 2)) + kb + b_colb;
                ldsm4(t, uBhi + off0);
                bhi[0][0] = t[0]; bhi[0][1] = t[1]; bhi[1][0] = t[2]; bhi[1][1] = t[3];
                ldsm4(t, uBhi + off1);
                bhi[2][0] = t[0]; bhi[2][1] = t[1]; bhi[3][0] = t[2]; bhi[3][1] = t[3];
                ldsm4(t, uBlo + off0);
                blo[0][0] = t[0]; blo[0][1] = t[1]; blo[1][0] = t[2]; blo[1][1] = t[3];
                ldsm4(t, uBlo + off1);
                blo[2][0] = t[0]; blo[2][1] = t[1]; blo[3][0] = t[2]; blo[3][1] = t[3];
            }
            #pragma unroll
            for (int mt = 0; mt < 4; mt++)
                #pragma unroll
                for (int nt = 0; nt < 4; nt++) {
                    mma16816(acc[mt][nt], ahi[mt], bhi[nt]);
                    mma16816(acc[mt][nt], ahi[mt], blo[nt]);
                    mma16816(acc[mt][nt], alo[mt], bhi[nt]);
                }
        }
        __syncthreads();
    }

    // ---- epilogue: bias add + store (float2 per fragment row) ----
    const int g  = lane >> 2;
    const int tg = lane & 3;
    #pragma unroll
    for (int nt = 0; nt < 4; nt++) {
        const int ncol = n0 + warp_n * 32 + nt * 8 + tg * 2;
        const float2 bv2 = *reinterpret_cast<const float2*>(bias + ncol);
        #pragma unroll
        for (int mt = 0; mt < 4; mt++) {
            const int m = m0 + warp_m * 64 + mt * 16 + g;
            float2 o0 = make_float2(acc[mt][nt][0] + bv2.x, acc[mt][nt][1] + bv2.y);
            float2 o1 = make_float2(acc[mt][nt][2] + bv2.x, acc[mt][nt][3] + bv2.y);
            *reinterpret_cast<float2*>(out + (size_t)m * H_DIM + ncol)       = o0;
            *reinterpret_cast<float2*>(out + (size_t)(m + 8) * H_DIM + ncol) = o1;
        }
    }
}

// ===========================================================================
// Fused attention (unchanged, proven R5 version): per (bh, q-tile of 128):
//   Phase 1: S = QK^T/8 + mask -> raw to W, online row max/sum.
//   Phase 2: normalize in place (final attn_weights) + P*V -> ctx.
// ===========================================================================
__global__ __launch_bounds__(256, 2) void attn_kernel(
    const int* __restrict__ mask, float* w, float* out_ctx)
{
    const int bh = blockIdx.y;
    const int b = bh >> 4;
    const int h = bh & 15;
    const int q0 = blockIdx.x * 128;
    const float* Qb = g_QL + (size_t)b * S_LEN * H_DIM + h * HDIM;
    const float* Kb = g_KL + (size_t)b * S_LEN * H_DIM + h * HDIM;
    const float* Vb = g_VL + (size_t)b * S_LEN * H_DIM + h * HDIM;
    float* W = w + (size_t)bh * S_LEN * S_LEN;

    __shared__ float As[16][132];
    __shared__ float Bs[16][132];
    __shared__ float sm_m[128];
    __shared__ float sm_il[128];

    const int tid = threadIdx.x;
    const int tx = tid & 15;
    const int ty = tid >> 4;

    float row_m[8], row_l[8];
    #pragma unroll
    for (int i = 0; i < 8; i++) { row_m[i] = -CUDART_INF_F; row_l[i] = 0.0f; }

    // ---------------- Phase 1: scores + online stats ----------------
    for (int kt = 0; kt < 8; kt++) {
        const int n0 = kt * 128;

        unsigned long long acc[8][4];
        #pragma unroll
        for (int i = 0; i < 8; i++)
            #pragma unroll
            for (int j = 0; j < 4; j++) acc[i][j] = 0ull;

        for (int k0 = 0; k0 < HDIM; k0 += 16) {
            #pragma unroll
            for (int l = 0; l < 2; l++) {
                int f = l * 256 + tid;
                int r = f >> 2, c4 = f & 3;
                const float4 v = *reinterpret_cast<const float4*>(
                    Qb + (size_t)(q0 + r) * H_DIM + k0 + c4 * 4);
                As[c4 * 4 + 0][r] = v.x; As[c4 * 4 + 1][r] = v.y;
                As[c4 * 4 + 2][r] = v.z; As[c4 * 4 + 3][r] = v.w;
            }
            #pragma unroll
            for (int l = 0; l < 2; l++) {
                int f = l * 256 + tid;
                int r = f >> 2, c4 = f & 3;
                const float4 v = *reinterpret_cast<const float4*>(
                    Kb + (size_t)(n0 + r) * H_DIM + k0 + c4 * 4);
                Bs[c4 * 4 + 0][r] = v.x; Bs[c4 * 4 + 1][r] = v.y;
                Bs[c4 * 4 + 2][r] = v.z; Bs[c4 * 4 + 3][r] = v.w;
            }
            __syncthreads();

            #pragma unroll
            for (int kk = 0; kk < 16; kk++) {
                float4 a0 = *reinterpret_cast<const float4*>(&As[kk][ty * 8]);
                float4 a1 = *reinterpret_cast<const float4*>(&As[kk][ty * 8 + 4]);
                unsigned long long aa[8];
                aa[0] = pack2(a0.x); aa[1] = pack2(a0.y); aa[2] = pack2(a0.z); aa[3] = pack2(a0.w);
                aa[4] = pack2(a1.x); aa[5] = pack2(a1.y); aa[6] = pack2(a1.z); aa[7] = pack2(a1.w);
                const unsigned long long* bp =
                    reinterpret_cast<const unsigned long long*>(&Bs[kk][tx * 8]);
                unsigned long long b0 = bp[0], b1 = bp[1], b2 = bp[2], b3 = bp[3];
                #pragma unroll
                for (int i = 0; i < 8; i++) {
                    acc[i][0] = ffma2(aa[i], b0, acc[i][0]);
                    acc[i][1] = ffma2(aa[i], b1, acc[i][1]);
                    acc[i][2] = ffma2(aa[i], b2, acc[i][2]);
                    acc[i][3] = ffma2(aa[i], b3, acc[i][3]);
                }
            }
            __syncthreads();
        }

        float madd[8];
        #pragma unroll
        for (int j = 0; j < 8; j++) {
            int n = n0 + tx * 8 + j;
            madd[j] = (mask[b * S_LEN + n] != 0) ? -1000000.0f : 0.0f;
        }

        float sacc[8][8];
        #pragma unroll
        for (int i = 0; i < 8; i++) {
            #pragma unroll
            for (int jj = 0; jj < 4; jj++) {
                float lo, hi;
                unpack2(acc[i][jj], lo, hi);
                sacc[i][2 * jj]     = lo * 0.125f + madd[2 * jj];
                sacc[i][2 * jj + 1] = hi * 0.125f + madd[2 * jj + 1];
            }
        }

        #pragma unroll
        for (int i = 0; i < 8; i++) {
            float tm = sacc[i][0];
            #pragma unroll
            for (int j = 1; j < 8; j++) tm = fmaxf(tm, sacc[i][j]);
            #pragma unroll
            for (int o = 8; o > 0; o >>= 1)
                tm = fmaxf(tm, __shfl_xor_sync(0xffffffffu, tm, o));
            float ts = 0.0f;
            #pragma unroll
            for (int j = 0; j < 8; j++) ts += __expf(sacc[i][j] - tm);
            #pragma unroll
            for (int o = 8; o > 0; o >>= 1)
                ts += __shfl_xor_sync(0xffffffffu, ts, o);

            float mn = fmaxf(row_m[i], tm);
            row_l[i] = row_l[i] * __expf(row_m[i] - mn) + ts * __expf(tm - mn);
            row_m[i] = mn;

            float4 s0 = make_float4(sacc[i][0], sacc[i][1], sacc[i][2], sacc[i][3]);
            float4 s1 = make_float4(sacc[i][4], sacc[i][5], sacc[i][6], sacc[i][7]);
            float* wp = W + (size_t)(q0 + ty * 8 + i) * S_LEN + n0 + tx * 8;
            *reinterpret_cast<float4*>(wp)     = s0;
            *reinterpret_cast<float4*>(wp + 4) = s1;
        }
    }

    if (tx == 0) {
        #pragma unroll
        for (int i = 0; i < 8; i++) {
            sm_m[ty * 8 + i]  = row_m[i];
            sm_il[ty * 8 + i] = 1.0f / row_l[i];
        }
    }
    __syncthreads();

    // ---------------- Phase 2: normalize + P*V ------
    unsigned long long cacc[8][2];
    #pragma unroll
    for (int i = 0; i < 8; i++) { cacc[i][0] = 0ull; cacc[i][1] = 0ull; }

    for (int k0 = 0; k0 < S_LEN; k0 += 16) {
        #pragma unroll
        for (int l = 0; l < 2; l++) {
            int f = l * 256 + tid;
            int r = f >> 2, c4 = f & 3;
            float* wp = W + (size_t)(q0 + r) * S_LEN + k0 + c4 * 4;
            float4 v = *reinterpret_cast<const float4*>(wp);
            const float mm = sm_m[r];
            const float il = sm_il[r];
            v.x = __expf(v.x - mm) * il;
            v.y = __expf(v.y - mm) * il;
            v.z = __expf(v.z - mm) * il;
            v.w = __expf(v.w - mm) * il;
            *reinterpret_cast<float4*>(wp) = v;
            As[c4 * 4 + 0][r] = v.x; As[c4 * 4 + 1][r] = v.y;
            As[c4 * 4 + 2][r] = v.z; As[c4 * 4 + 3][r] = v.w;
        }
        {
            int r = tid >> 4, c4 = tid & 15;
            const float4 v = *reinterpret_cast<const float4*>(
                Vb + (size_t)(k0 + r) * H_DIM + c4 * 4);
            *reinterpret_cast<float4*>(&Bs[r][c4 * 4]) = v;
        }
        __syncthreads();

        #pragma unroll
        for (int kk = 0; kk < 16; kk++) {
            float4 a0 = *reinterpret_cast<const float4*>(&As[kk][ty * 8]);
            float4 a1 = *reinterpret_cast<const float4*>(&As[kk][ty * 8 + 4]);
            unsigned long long aa[8];
            aa[0] = pack2(a0.x); aa[1] = pack2(a0.y); aa[2] = pack2(a0.z); aa[3] = pack2(a0.w);
            aa[4] = pack2(a1.x); aa[5] = pack2(a1.y); aa[6] = pack2(a1.z); aa[7] = pack2(a1.w);
            const unsigned long long* bp =
                reinterpret_cast<const unsigned long long*>(&Bs[kk][tx * 4]);
            unsigned long long b0 = bp[0], b1 = bp[1];
            #pragma unroll
            for (int i = 0; i < 8; i++) {
                cacc[i][0] = ffma2(aa[i], b0, cacc[i][0]);
                cacc[i][1] = ffma2(aa[i], b1, cacc[i][1]);
            }
        }
        __syncthreads();
    }

    #pragma unroll
    for (int i = 0; i < 8; i++) {
        int s = q0 + ty * 8 + i;
        float lo, hi;
        float4 o;
        unpack2(cacc[i][0], lo, hi); o.x = lo; o.y = hi;
        unpack2(cacc[i][1], lo, hi); o.z = lo; o.w = hi;
        *reinterpret_cast<float4*>(
            out_ctx + ((size_t)s * B_SZ + b) * H_DIM + h * HDIM + tx * 4) = o;
    }
}

// ---------------------------------------------------------------------------
// Launch
// ---------------------------------------------------------------------------
extern "C" void kernel_launch(void* const* d_in, const int* in_sizes, int n_in,
                              void* d_out, int out_size)
{
    const float* q_states = (const float*)d_in[0];
    const float* k_states = (const float*)d_in[1];
    const float* v_states = (const float*)d_in[2];
    const int*   mask     = (const int*)  d_in[3];
    const float* Wq = (const float*)d_in[4];
    const float* bq = (const float*)d_in[5];
    const float* Wk = (const float*)d_in[6];
    const float* bk = (const float*)d_in[7];
    const float* Wv = (const float*)d_in[8];
    const float* bv = (const float*)d_in[9];

    float* out_ctx = (float*)d_out;                           // [S, B, H]
    float* out_w   = out_ctx + (size_t)S_LEN * B_SZ * H_DIM;  // [B, NH, S, S]

    dim3 pg(H_DIM / 128, M_ROWS / 128, 3);   // (8, 64, 3)
    proj_mma_kernel<<<pg, 256>>>(
        q_states, k_states, v_states, Wq, bq, Wk, bk, Wv, bv);

    dim3 ag(S_LEN / 128, B_SZ * NHEAD);      // (8, 128)
    attn_kernel<<<ag, 256>>>(mask, out_w, out_ctx);
}